// round 1
// baseline (speedup 1.0000x reference)
#include <cuda_runtime.h>
#include <math.h>

// Problem constants
#define BB 8
#define LL 64
#define FFdim 16
#define CC 128
#define HH 8
#define FFN 512
#define PP 1024            // L*F positions per batch
#define NTOK 8192          // B*P tokens
#define CH 1024            // C*H

// ---------------------------------------------------------------------------
// Scratch: one big static device buffer, offsets in floats
// ---------------------------------------------------------------------------
#define OFF_Q   0L
#define SZ_QKV  (8L * 8 * 1024 * 128)          // 8,388,608
#define OFF_K   (OFF_Q + SZ_QKV)
#define OFF_V   (OFF_K + SZ_QKV)
#define OFF_S   (OFF_V + SZ_QKV)
#define SZ_S    (64L * 1024 * 1024)            // 67,108,864
#define OFF_ZC  (OFF_S + SZ_S)
#define SZ_ZC   (8192L * 1024)
#define OFF_AO  (OFF_ZC + SZ_ZC)
#define SZ_TOK  (8192L * 128)
#define OFF_Z1  (OFF_AO + SZ_TOK)
#define OFF_H1  (OFF_Z1 + SZ_TOK)
#define SZ_H1   (8192L * 512)
#define OFF_FFY (OFF_H1 + SZ_H1)
#define SCRATCH_TOTAL (OFF_FFY + SZ_TOK)

__device__ float g_scratch[SCRATCH_TOTAL];

// ---------------------------------------------------------------------------
// Generic tiled SGEMM: C = act(scale * A @ B^T + bias), 128x128 tile, K-step 8
// A: (M x K) row-major (+ batch stride sA)
// B: if !B_KMAJOR: (N x K) row-major; if B_KMAJOR: (K x N) row-major
// OUTMAP: 0 plain row-major (ldc, sC); 1 QKV head-scatter; 2 AV head-recombine
// ---------------------------------------------------------------------------
template<int OUTMAP, bool B_KMAJOR, bool RELU>
__global__ __launch_bounds__(256, 2) void sgemm(
    const float* __restrict__ A, int lda, long sA,
    const float* __restrict__ Bm, int ldb, long sB,
    const float* __restrict__ bias,
    float* __restrict__ Co, int ldc, long sC,
    int K, float scale)
{
    const int bz = blockIdx.z;
    A  += (long)bz * sA;
    Bm += (long)bz * sB;

    __shared__ float As[8][132];
    __shared__ float Bs[8][132];

    const int t  = threadIdx.x;
    const int m0 = blockIdx.y << 7;
    const int n0 = blockIdx.x << 7;

    const int rb = (t >> 4) << 3;   // row base within tile (0..120)
    const int cb = (t & 15) << 3;   // col base within tile

    // loader indices: 256 threads load 128x8 tile (4 floats each, float4)
    const int lr = t >> 1;          // 0..127
    const int lk = (t & 1) << 2;    // 0 or 4

    float acc[8][8];
#pragma unroll
    for (int i = 0; i < 8; i++)
#pragma unroll
        for (int j = 0; j < 8; j++) acc[i][j] = 0.f;

    for (int k0 = 0; k0 < K; k0 += 8) {
        // --- A tile ---
        {
            float4 av = *(const float4*)(A + (long)(m0 + lr) * lda + (k0 + lk));
            As[lk + 0][lr] = av.x;
            As[lk + 1][lr] = av.y;
            As[lk + 2][lr] = av.z;
            As[lk + 3][lr] = av.w;
        }
        // --- B tile ---
        if (B_KMAJOR) {
            int kk = t >> 5;            // 0..7
            int n4 = (t & 31) << 2;     // 0..124
            float4 bv = *(const float4*)(Bm + (long)(k0 + kk) * ldb + (n0 + n4));
            *(float4*)&Bs[kk][n4] = bv;
        } else {
            float4 bv = *(const float4*)(Bm + (long)(n0 + lr) * ldb + (k0 + lk));
            Bs[lk + 0][lr] = bv.x;
            Bs[lk + 1][lr] = bv.y;
            Bs[lk + 2][lr] = bv.z;
            Bs[lk + 3][lr] = bv.w;
        }
        __syncthreads();

#pragma unroll
        for (int kk = 0; kk < 8; kk++) {
            float a[8], b[8];
            *(float4*)(a)     = *(const float4*)&As[kk][rb];
            *(float4*)(a + 4) = *(const float4*)&As[kk][rb + 4];
            *(float4*)(b)     = *(const float4*)&Bs[kk][cb];
            *(float4*)(b + 4) = *(const float4*)&Bs[kk][cb + 4];
#pragma unroll
            for (int i = 0; i < 8; i++)
#pragma unroll
                for (int j = 0; j < 8; j++)
                    acc[i][j] = fmaf(a[i], b[j], acc[i][j]);
        }
        __syncthreads();
    }

    // --- epilogue ---
#pragma unroll
    for (int i = 0; i < 8; i++) {
        const int m = m0 + rb + i;
#pragma unroll
        for (int j = 0; j < 8; j++) {
            const int n = n0 + cb + j;
            float v = acc[i][j] * scale;
            if (bias) v += bias[n];
            if (RELU) v = fmaxf(v, 0.f);
            long off;
            if constexpr (OUTMAP == 0) {
                off = (long)bz * sC + (long)m * ldc + n;
            } else if constexpr (OUTMAP == 1) {
                // m = b*P + p ; n = cq*H + h ; out[((b*H+h)*P+p)*C + cq]
                int b  = m >> 10, p = m & 1023;
                int cq = n >> 3,  h = n & 7;
                off = (((long)(b * HH + h) * PP + p) << 7) + cq;
            } else {
                // bz = b*H + h ; out[(b*P+m)*CH + n*H + h]
                int b = bz >> 3, h = bz & 7;
                off = ((long)(b * PP + m) << 10) + (n << 3) + h;
            }
            Co[off] = v;
        }
    }
}

// ---------------------------------------------------------------------------
// Double softmax over one (bh, query) row of 1024 = (m=64, g=16) scores.
// First softmax over m (per g), then softmax over g (per m) of the result.
// ---------------------------------------------------------------------------
__global__ __launch_bounds__(128) void softmax2_kernel(float* __restrict__ S)
{
    float* row = S + ((long)blockIdx.y * PP + blockIdx.x) * PP;
    __shared__ float sp[64 * 17];   // [m][g] padded stride 17
    const int t = threadIdx.x;

    // load 8 consecutive cols: col = t*8 + i -> m = t/2, g = (t&1)*8 + i
    float4 v0 = *(const float4*)(row + t * 8);
    float4 v1 = *(const float4*)(row + t * 8 + 4);
    float* dst = sp + (t >> 1) * 17 + ((t & 1) << 3);
    dst[0] = v0.x; dst[1] = v0.y; dst[2] = v0.z; dst[3] = v0.w;
    dst[4] = v1.x; dst[5] = v1.y; dst[6] = v1.z; dst[7] = v1.w;
    __syncthreads();

    // phase 1: softmax over m for each g. 8 threads per g (aligned shfl group)
    {
        const int g = t >> 3, ii = t & 7;
        float mx = -1e30f;
#pragma unroll
        for (int jm = ii; jm < 64; jm += 8) mx = fmaxf(mx, sp[jm * 17 + g]);
#pragma unroll
        for (int o = 4; o; o >>= 1) mx = fmaxf(mx, __shfl_xor_sync(0xffffffffu, mx, o));
        float sum = 0.f;
#pragma unroll
        for (int jm = ii; jm < 64; jm += 8) {
            float e = __expf(sp[jm * 17 + g] - mx);
            sp[jm * 17 + g] = e;
            sum += e;
        }
#pragma unroll
        for (int o = 4; o; o >>= 1) sum += __shfl_xor_sync(0xffffffffu, sum, o);
        float inv = 1.f / sum;
#pragma unroll
        for (int jm = ii; jm < 64; jm += 8) sp[jm * 17 + g] *= inv;
    }
    __syncthreads();

    // phase 2: softmax over g for each m. one thread per m (stride-17 rows: conflict-free)
    if (t < 64) {
        float* r = sp + t * 17;
        float mx2 = -1e30f;
#pragma unroll
        for (int g2 = 0; g2 < 16; g2++) mx2 = fmaxf(mx2, r[g2]);
        float s2 = 0.f;
#pragma unroll
        for (int g2 = 0; g2 < 16; g2++) {
            float e = __expf(r[g2] - mx2);
            r[g2] = e;
            s2 += e;
        }
        float i2 = 1.f / s2;
#pragma unroll
        for (int g2 = 0; g2 < 16; g2++) r[g2] *= i2;
    }
    __syncthreads();

    // store back (same mapping)
    const float* src = sp + (t >> 1) * 17 + ((t & 1) << 3);
    float4 o0 = make_float4(src[0], src[1], src[2], src[3]);
    float4 o1 = make_float4(src[4], src[5], src[6], src[7]);
    *(float4*)(row + t * 8)     = o0;
    *(float4*)(row + t * 8 + 4) = o1;
}

// ---------------------------------------------------------------------------
// out = LayerNorm(A + R) * gamma + beta  — one block (128 threads) per token
// ---------------------------------------------------------------------------
__global__ __launch_bounds__(128) void add_ln_kernel(
    const float* __restrict__ A, const float* __restrict__ R,
    const float* __restrict__ gam, const float* __restrict__ bet,
    float* __restrict__ out)
{
    const long base = (long)blockIdx.x * CC;
    const int t = threadIdx.x;
    __shared__ float red[8];

    float v = A[base + t] + R[base + t];

    float s = v;
#pragma unroll
    for (int o = 16; o; o >>= 1) s += __shfl_xor_sync(0xffffffffu, s, o);
    if ((t & 31) == 0) red[t >> 5] = s;
    __syncthreads();
    const float mean = (red[0] + red[1] + red[2] + red[3]) * (1.f / CC);

    const float d = v - mean;
    float s2 = d * d;
#pragma unroll
    for (int o = 16; o; o >>= 1) s2 += __shfl_xor_sync(0xffffffffu, s2, o);
    if ((t & 31) == 0) red[4 + (t >> 5)] = s2;
    __syncthreads();
    const float var = (red[4] + red[5] + red[6] + red[7]) * (1.f / CC);

    out[base + t] = d * rsqrtf(var + 1e-5f) * gam[t] + bet[t];
}

// ---------------------------------------------------------------------------
extern "C" void kernel_launch(void* const* d_in, const int* in_sizes, int n_in,
                              void* d_out, int out_size)
{
    const float* x     = (const float*)d_in[0];
    const float* wq    = (const float*)d_in[1];
    const float* bq    = (const float*)d_in[2];
    const float* wk    = (const float*)d_in[3];
    const float* bk    = (const float*)d_in[4];
    const float* wv    = (const float*)d_in[5];
    const float* bv    = (const float*)d_in[6];
    const float* wo    = (const float*)d_in[7];
    const float* bo    = (const float*)d_in[8];
    const float* ln1_g = (const float*)d_in[9];
    const float* ln1_b = (const float*)d_in[10];
    const float* w1    = (const float*)d_in[11];
    const float* b1    = (const float*)d_in[12];
    const float* w2    = (const float*)d_in[13];
    const float* b2    = (const float*)d_in[14];
    const float* ln2_g = (const float*)d_in[15];
    const float* ln2_b = (const float*)d_in[16];
    float* out = (float*)d_out;

    float* scr = nullptr;
    cudaGetSymbolAddress((void**)&scr, g_scratch);
    float* q   = scr + OFF_Q;
    float* k   = scr + OFF_K;
    float* v   = scr + OFF_V;
    float* sS  = scr + OFF_S;
    float* zc  = scr + OFF_ZC;
    float* ao  = scr + OFF_AO;
    float* z1  = scr + OFF_Z1;
    float* h1  = scr + OFF_H1;
    float* ffy = scr + OFF_FFY;

    const float inv_sqrt_c = 0.08838834764831845f;   // 1/sqrt(128)

    // 1-3: QKV projections (M=8192, N=1024, K=128) with head-scatter epilogue
    sgemm<1, false, false><<<dim3(8, 64, 1), 256>>>(
        x, CC, 0, wq, CC, 0, bq, q, 0, 0, CC, 1.f);
    sgemm<1, false, false><<<dim3(8, 64, 1), 256>>>(
        x, CC, 0, wk, CC, 0, bk, k, 0, 0, CC, 1.f);
    sgemm<1, false, false><<<dim3(8, 64, 1), 256>>>(
        x, CC, 0, wv, CC, 0, bv, v, 0, 0, CC, 1.f);

    // 4: scores = Q @ K^T * 1/sqrt(C)   (64 batches of 1024x1024x128)
    sgemm<0, false, false><<<dim3(8, 8, 64), 256>>>(
        q, CC, (long)PP * CC, k, CC, (long)PP * CC, nullptr,
        sS, PP, (long)PP * PP, CC, inv_sqrt_c);

    // 5: double softmax (per bh, per query row)
    softmax2_kernel<<<dim3(PP, 64), 128>>>(sS);

    // 6: Z = A @ V (64 batches of 1024x128x1024), head-recombine epilogue -> zc
    sgemm<2, true, false><<<dim3(1, 8, 64), 256>>>(
        sS, PP, (long)PP * PP, v, CC, (long)PP * CC, nullptr,
        zc, 0, 0, PP, 1.f);

    // 7: attn_out = zc @ wo^T + bo  (8192x128x1024)
    sgemm<0, false, false><<<dim3(1, 64, 1), 256>>>(
        zc, CH, 0, wo, CH, 0, bo, ao, CC, 0, CH, 1.f);

    // 8: z1 = LN1(attn_out + x)
    add_ln_kernel<<<NTOK, 128>>>(ao, x, ln1_g, ln1_b, z1);

    // 9: h1 = relu(z1 @ w1^T + b1)  (8192x512x128)
    sgemm<0, false, true><<<dim3(4, 64, 1), 256>>>(
        z1, CC, 0, w1, CC, 0, b1, h1, FFN, 0, CC, 1.f);

    // 10: ffy = h1 @ w2^T + b2  (8192x128x512)
    sgemm<0, false, false><<<dim3(1, 64, 1), 256>>>(
        h1, FFN, 0, w2, FFN, 0, b2, ffy, CC, 0, FFN, 1.f);

    // 11: out = LN2(ffy + z1)
    add_ln_kernel<<<NTOK, 128>>>(ffy, z1, ln2_g, ln2_b, out);
}

// round 4
// speedup vs baseline: 1.9857x; 1.9857x over previous
#include <cuda_runtime.h>
#include <cstdint>
#include <math.h>

// Problem constants
#define BB 8
#define CC 128
#define HH 8
#define FFN 512
#define PP 1024            // L*F positions per batch
#define NTOK 8192          // B*P tokens
#define CH 1024            // C*H

// ---------------------------------------------------------------------------
// Scratch
// ---------------------------------------------------------------------------
#define OFF_Q   0L
#define SZ_QKV  (8L * 8 * 1024 * 128)
#define OFF_K   (OFF_Q + SZ_QKV)
#define OFF_V   (OFF_K + SZ_QKV)           // V stored TRANSPOSED: (bh, c, p)
#define OFF_S   (OFF_V + SZ_QKV)
#define SZ_S    (64L * 1024 * 1024)
#define OFF_ZC  (OFF_S + SZ_S)
#define SZ_ZC   (8192L * 1024)
#define OFF_AO  (OFF_ZC + SZ_ZC)
#define SZ_TOK  (8192L * 128)
#define OFF_Z1  (OFF_AO + SZ_TOK)
#define OFF_H1  (OFF_Z1 + SZ_TOK)
#define SZ_H1   (8192L * 512)
#define OFF_FFY (OFF_H1 + SZ_H1)
#define SCRATCH_TOTAL (OFF_FFY + SZ_TOK)

__device__ float g_scratch[SCRATCH_TOTAL];

// ---------------------------------------------------------------------------
// mma.sync m16n8k8 tf32 helper
// ---------------------------------------------------------------------------
__device__ __forceinline__ void mma_tf32(
    float& c0, float& c1, float& c2, float& c3,
    uint32_t a0, uint32_t a1, uint32_t a2, uint32_t a3,
    uint32_t b0, uint32_t b1)
{
    asm volatile(
        "mma.sync.aligned.m16n8k8.row.col.f32.tf32.tf32.f32 "
        "{%0,%1,%2,%3}, {%4,%5,%6,%7}, {%8,%9}, {%0,%1,%2,%3};"
        : "+f"(c0), "+f"(c1), "+f"(c2), "+f"(c3)
        : "r"(a0), "r"(a1), "r"(a2), "r"(a3), "r"(b0), "r"(b1));
}

__device__ __forceinline__ uint32_t f2tf32(float x) {
    uint32_t u;
    asm("cvt.rna.tf32.f32 %0, %1;" : "=r"(u) : "f"(x));
    return u;
}

// SMEM: As/Bs double-buffered, layout [row 0..127][k 0..31] padded to 36 floats
#define LDP 36
#define TILE_F (128 * LDP)                  // floats per tile buffer
#define SMEM_FLOATS (4 * TILE_F)            // A0,A1,B0,B1
#define SMEM_BYTES (SMEM_FLOATS * 4)        // 73728

// ---------------------------------------------------------------------------
// TF32 tensor-core GEMM: D(128x128 tile) = act(scale * A @ B^T + bias)
// A: (M x K) row-major fp32 (+ bz*sA). B: (N x K) row-major fp32 (+ bz*sB).
// OUTMAP: 0 plain (ldc,sC); 1 QKV head-scatter; 2 AV head-recombine; 3 V-transpose
// ---------------------------------------------------------------------------
template<int OUTMAP, bool RELU>
__global__ __launch_bounds__(256) void tgemm(
    const float* __restrict__ A, int lda, long sA,
    const float* __restrict__ Bm, int ldb, long sB,
    const float* __restrict__ bias,
    float* __restrict__ Co, int ldc, long sC,
    int K, float scale)
{
    extern __shared__ float sm[];
    float* As[2] = { sm,              sm + TILE_F };
    float* Bs[2] = { sm + 2 * TILE_F, sm + 3 * TILE_F };

    const int t   = threadIdx.x;
    const int wid = t >> 5;
    const int lid = t & 31;
    const int g   = lid >> 2;       // 0..7
    const int t4  = lid & 3;        // 0..3
    const int wm  = wid & 3;        // warp row 0..3  -> rows wm*32..wm*32+31
    const int wn  = wid >> 2;       // warp col 0..1  -> cols wn*64..wn*64+63

    const int bz = blockIdx.z;
    const int m0 = blockIdx.y << 7;
    const int n0 = blockIdx.x << 7;
    A  += (long)bz * sA;
    Bm += (long)bz * sB;

    float acc[2][8][4];
#pragma unroll
    for (int mt = 0; mt < 2; mt++)
#pragma unroll
        for (int nt = 0; nt < 8; nt++)
#pragma unroll
            for (int i = 0; i < 4; i++) acc[mt][nt][i] = 0.f;

    const int nch = K >> 5;

    // per-thread tile element assignment: idx = i*256 + t ; row = idx>>3, k4 = idx&7
    const int r_ld  = t >> 3;              // base row for i=0 (rows advance by 32 per i)
    const int k4_ld = t & 7;

    auto gload = [&](const float* __restrict__ G, int ld, int row0, int k0, float4* pr) {
#pragma unroll
        for (int i = 0; i < 4; i++)
            pr[i] = *(const float4*)(G + (long)(row0 + r_ld + i * 32) * ld + k0 + (k4_ld << 2));
    };
    auto sstore = [&](float* S, const float4* pr) {
#pragma unroll
        for (int i = 0; i < 4; i++) {
            float4 v = pr[i];
            float4 w;
            w.x = __uint_as_float(f2tf32(v.x));
            w.y = __uint_as_float(f2tf32(v.y));
            w.z = __uint_as_float(f2tf32(v.z));
            w.w = __uint_as_float(f2tf32(v.w));
            *(float4*)(S + (r_ld + i * 32) * LDP + (k4_ld << 2)) = w;
        }
    };

    float4 pa[4], pb[4];

    // preload chunk 0
    gload(A, lda, m0, 0, pa);
    gload(Bm, ldb, n0, 0, pb);
    sstore(As[0], pa);
    sstore(Bs[0], pb);
    __syncthreads();

    for (int c = 0; c < nch; c++) {
        const int cur = c & 1;
        if (c + 1 < nch) {
            gload(A, lda, m0, (c + 1) << 5, pa);
            gload(Bm, ldb, n0, (c + 1) << 5, pb);
        }

        const float* Ab = As[cur];
        const float* Bb = Bs[cur];
#pragma unroll
        for (int kk = 0; kk < 4; kk++) {
            uint32_t af[2][4];
#pragma unroll
            for (int mt = 0; mt < 2; mt++) {
                const float* ar = Ab + (wm * 32 + mt * 16 + g) * LDP + kk * 8 + t4;
                af[mt][0] = __float_as_uint(ar[0]);
                af[mt][1] = __float_as_uint(ar[8 * LDP]);
                af[mt][2] = __float_as_uint(ar[4]);
                af[mt][3] = __float_as_uint(ar[8 * LDP + 4]);
            }
#pragma unroll
            for (int nt = 0; nt < 8; nt++) {
                const float* br = Bb + (wn * 64 + nt * 8 + g) * LDP + kk * 8 + t4;
                uint32_t b0 = __float_as_uint(br[0]);
                uint32_t b1 = __float_as_uint(br[4]);
#pragma unroll
                for (int mt = 0; mt < 2; mt++)
                    mma_tf32(acc[mt][nt][0], acc[mt][nt][1], acc[mt][nt][2], acc[mt][nt][3],
                             af[mt][0], af[mt][1], af[mt][2], af[mt][3], b0, b1);
            }
        }

        if (c + 1 < nch) {
            sstore(As[cur ^ 1], pa);
            sstore(Bs[cur ^ 1], pb);
        }
        __syncthreads();
    }

    // ---------------- epilogue ----------------
    auto outoff = [&](int m, int n) -> long {
        if constexpr (OUTMAP == 0) {
            return (long)bz * sC + (long)m * ldc + n;
        } else if constexpr (OUTMAP == 1) {
            int b = m >> 10, p = m & 1023;
            int cq = n >> 3, h = n & 7;
            return (((long)(b * HH + h) * PP + p) << 7) + cq;
        } else if constexpr (OUTMAP == 2) {
            int b = bz >> 3, h = bz & 7;
            return ((long)(b * PP + m) << 10) + (n << 3) + h;
        } else {
            int b = m >> 10, p = m & 1023;
            int cq = n >> 3, h = n & 7;
            return (((long)(b * HH + h) * CC + cq) << 10) + p;
        }
    };

#pragma unroll
    for (int mt = 0; mt < 2; mt++) {
        const int r0 = m0 + wm * 32 + mt * 16 + g;
#pragma unroll
        for (int nt = 0; nt < 8; nt++) {
            const int col = n0 + wn * 64 + nt * 8 + t4 * 2;
            float v0 = acc[mt][nt][0] * scale;
            float v1 = acc[mt][nt][1] * scale;
            float v2 = acc[mt][nt][2] * scale;
            float v3 = acc[mt][nt][3] * scale;
            if (bias) {
                float bi0 = bias[col], bi1 = bias[col + 1];
                v0 += bi0; v1 += bi1; v2 += bi0; v3 += bi1;
            }
            if (RELU) {
                v0 = fmaxf(v0, 0.f); v1 = fmaxf(v1, 0.f);
                v2 = fmaxf(v2, 0.f); v3 = fmaxf(v3, 0.f);
            }
            if constexpr (OUTMAP == 0) {
                *(float2*)(Co + outoff(r0, col))     = make_float2(v0, v1);
                *(float2*)(Co + outoff(r0 + 8, col)) = make_float2(v2, v3);
            } else {
                Co[outoff(r0, col)]         = v0;
                Co[outoff(r0, col + 1)]     = v1;
                Co[outoff(r0 + 8, col)]     = v2;
                Co[outoff(r0 + 8, col + 1)] = v3;
            }
        }
    }
}

// ---------------------------------------------------------------------------
// Double softmax over one (bh, query) row: 1024 = (m=64, g=16).
// ---------------------------------------------------------------------------
__global__ __launch_bounds__(128) void softmax2_kernel(float* __restrict__ S)
{
    float* row = S + ((long)blockIdx.y * PP + blockIdx.x) * PP;
    __shared__ float sp[64 * 17];
    const int t = threadIdx.x;

    float4 v0 = *(const float4*)(row + t * 8);
    float4 v1 = *(const float4*)(row + t * 8 + 4);
    float* dst = sp + (t >> 1) * 17 + ((t & 1) << 3);
    dst[0] = v0.x; dst[1] = v0.y; dst[2] = v0.z; dst[3] = v0.w;
    dst[4] = v1.x; dst[5] = v1.y; dst[6] = v1.z; dst[7] = v1.w;
    __syncthreads();

    {
        const int g = t >> 3, ii = t & 7;
        float mx = -1e30f;
#pragma unroll
        for (int jm = ii; jm < 64; jm += 8) mx = fmaxf(mx, sp[jm * 17 + g]);
#pragma unroll
        for (int o = 4; o; o >>= 1) mx = fmaxf(mx, __shfl_xor_sync(0xffffffffu, mx, o));
        float sum = 0.f;
#pragma unroll
        for (int jm = ii; jm < 64; jm += 8) {
            float e = __expf(sp[jm * 17 + g] - mx);
            sp[jm * 17 + g] = e;
            sum += e;
        }
#pragma unroll
        for (int o = 4; o; o >>= 1) sum += __shfl_xor_sync(0xffffffffu, sum, o);
        float inv = 1.f / sum;
#pragma unroll
        for (int jm = ii; jm < 64; jm += 8) sp[jm * 17 + g] *= inv;
    }
    __syncthreads();

    if (t < 64) {
        float* r = sp + t * 17;
        float mx2 = -1e30f;
#pragma unroll
        for (int g2 = 0; g2 < 16; g2++) mx2 = fmaxf(mx2, r[g2]);
        float s2 = 0.f;
#pragma unroll
        for (int g2 = 0; g2 < 16; g2++) {
            float e = __expf(r[g2] - mx2);
            r[g2] = e;
            s2 += e;
        }
        float i2 = 1.f / s2;
#pragma unroll
        for (int g2 = 0; g2 < 16; g2++) r[g2] *= i2;
    }
    __syncthreads();

    const float* src = sp + (t >> 1) * 17 + ((t & 1) << 3);
    *(float4*)(row + t * 8)     = make_float4(src[0], src[1], src[2], src[3]);
    *(float4*)(row + t * 8 + 4) = make_float4(src[4], src[5], src[6], src[7]);
}

// ---------------------------------------------------------------------------
// out = LayerNorm(A + R) * gamma + beta
// ---------------------------------------------------------------------------
__global__ __launch_bounds__(128) void add_ln_kernel(
    const float* __restrict__ A, const float* __restrict__ R,
    const float* __restrict__ gam, const float* __restrict__ bet,
    float* __restrict__ out)
{
    const long base = (long)blockIdx.x * CC;
    const int t = threadIdx.x;
    __shared__ float red[8];

    float v = A[base + t] + R[base + t];

    float s = v;
#pragma unroll
    for (int o = 16; o; o >>= 1) s += __shfl_xor_sync(0xffffffffu, s, o);
    if ((t & 31) == 0) red[t >> 5] = s;
    __syncthreads();
    const float mean = (red[0] + red[1] + red[2] + red[3]) * (1.f / CC);

    const float d = v - mean;
    float s2 = d * d;
#pragma unroll
    for (int o = 16; o; o >>= 1) s2 += __shfl_xor_sync(0xffffffffu, s2, o);
    if ((t & 31) == 0) red[4 + (t >> 5)] = s2;
    __syncthreads();
    const float var = (red[4] + red[5] + red[6] + red[7]) * (1.f / CC);

    out[base + t] = d * rsqrtf(var + 1e-5f) * gam[t] + bet[t];
}

// ---------------------------------------------------------------------------
extern "C" void kernel_launch(void* const* d_in, const int* in_sizes, int n_in,
                              void* d_out, int out_size)
{
    const float* x     = (const float*)d_in[0];
    const float* wq    = (const float*)d_in[1];
    const float* bq    = (const float*)d_in[2];
    const float* wk    = (const float*)d_in[3];
    const float* bk    = (const float*)d_in[4];
    const float* wv    = (const float*)d_in[5];
    const float* bv    = (const float*)d_in[6];
    const float* wo    = (const float*)d_in[7];
    const float* bo    = (const float*)d_in[8];
    const float* ln1_g = (const float*)d_in[9];
    const float* ln1_b = (const float*)d_in[10];
    const float* w1    = (const float*)d_in[11];
    const float* b1    = (const float*)d_in[12];
    const float* w2    = (const float*)d_in[13];
    const float* b2    = (const float*)d_in[14];
    const float* ln2_g = (const float*)d_in[15];
    const float* ln2_b = (const float*)d_in[16];
    float* out = (float*)d_out;

    float* scr = nullptr;
    cudaGetSymbolAddress((void**)&scr, g_scratch);
    float* q   = scr + OFF_Q;
    float* k   = scr + OFF_K;
    float* vt  = scr + OFF_V;
    float* sS  = scr + OFF_S;
    float* zc  = scr + OFF_ZC;
    float* ao  = scr + OFF_AO;
    float* z1  = scr + OFF_Z1;
    float* h1  = scr + OFF_H1;
    float* ffy = scr + OFF_FFY;

    cudaFuncSetAttribute(tgemm<0, false>, cudaFuncAttributeMaxDynamicSharedMemorySize, SMEM_BYTES);
    cudaFuncSetAttribute(tgemm<0, true>,  cudaFuncAttributeMaxDynamicSharedMemorySize, SMEM_BYTES);
    cudaFuncSetAttribute(tgemm<1, false>, cudaFuncAttributeMaxDynamicSharedMemorySize, SMEM_BYTES);
    cudaFuncSetAttribute(tgemm<2, false>, cudaFuncAttributeMaxDynamicSharedMemorySize, SMEM_BYTES);
    cudaFuncSetAttribute(tgemm<3, false>, cudaFuncAttributeMaxDynamicSharedMemorySize, SMEM_BYTES);

    const float inv_sqrt_c = 0.08838834764831845f;

    // 1-3: QKV projections (8192 x 1024 x 128)
    tgemm<1, false><<<dim3(8, 64, 1), 256, SMEM_BYTES>>>(
        x, CC, 0, wq, CC, 0, bq, q, 0, 0, CC, 1.f);
    tgemm<1, false><<<dim3(8, 64, 1), 256, SMEM_BYTES>>>(
        x, CC, 0, wk, CC, 0, bk, k, 0, 0, CC, 1.f);
    tgemm<3, false><<<dim3(8, 64, 1), 256, SMEM_BYTES>>>(
        x, CC, 0, wv, CC, 0, bv, vt, 0, 0, CC, 1.f);

    // 4: scores = Q @ K^T / sqrt(C)  (64 batches of 1024x1024x128)
    tgemm<0, false><<<dim3(8, 8, 64), 256, SMEM_BYTES>>>(
        q, CC, (long)PP * CC, k, CC, (long)PP * CC, nullptr,
        sS, PP, (long)PP * PP, CC, inv_sqrt_c);

    // 5: double softmax
    softmax2_kernel<<<dim3(PP, 64), 128>>>(sS);

    // 6: Z = A @ Vt^T  (64 batches of 1024x128x1024), head-recombine -> zc
    tgemm<2, false><<<dim3(1, 8, 64), 256, SMEM_BYTES>>>(
        sS, PP, (long)PP * PP, vt, PP, (long)CC * PP, nullptr,
        zc, 0, 0, PP, 1.f);

    // 7: attn_out = zc @ wo^T + bo  (8192x128x1024)
    tgemm<0, false><<<dim3(1, 64, 1), 256, SMEM_BYTES>>>(
        zc, CH, 0, wo, CH, 0, bo, ao, CC, 0, CH, 1.f);

    // 8: z1 = LN1(attn_out + x)
    add_ln_kernel<<<NTOK, 128>>>(ao, x, ln1_g, ln1_b, z1);

    // 9: h1 = relu(z1 @ w1^T + b1)  (8192x512x128)
    tgemm<0, true><<<dim3(4, 64, 1), 256, SMEM_BYTES>>>(
        z1, CC, 0, w1, CC, 0, b1, h1, FFN, 0, CC, 1.f);

    // 10: ffy = h1 @ w2^T + b2  (8192x128x512)
    tgemm<0, false><<<dim3(1, 64, 1), 256, SMEM_BYTES>>>(
        h1, FFN, 0, w2, FFN, 0, b2, ffy, CC, 0, FFN, 1.f);

    // 11: out = LN2(ffy + z1)
    add_ln_kernel<<<NTOK, 128>>>(ffy, z1, ln2_g, ln2_b, out);
}

// round 7
// speedup vs baseline: 2.7397x; 1.3797x over previous
#include <cuda_runtime.h>
#include <cstdint>
#include <math.h>

// Problem constants
#define BB 8
#define CC 128
#define HH 8
#define FFN 512
#define PP 1024            // L*F positions per batch
#define NTOK 8192          // B*P tokens
#define CH 1024            // C*H

// ---------------------------------------------------------------------------
// Scratch
// ---------------------------------------------------------------------------
#define OFF_Q   0L
#define SZ_QKV  (8L * 8 * 1024 * 128)
#define OFF_K   (OFF_Q + SZ_QKV)
#define OFF_V   (OFF_K + SZ_QKV)           // V stored TRANSPOSED: (bh, c, p)
#define OFF_S   (OFF_V + SZ_QKV)
#define SZ_S    (64L * 1024 * 1024)
#define OFF_ZC  (OFF_S + SZ_S)
#define SZ_ZC   (8192L * 1024)
#define OFF_AO  (OFF_ZC + SZ_ZC)
#define SZ_TOK  (8192L * 128)
#define OFF_Z1  (OFF_AO + SZ_TOK)
#define OFF_H1  (OFF_Z1 + SZ_TOK)
#define SZ_H1   (8192L * 512)
#define OFF_FFY (OFF_H1 + SZ_H1)
#define SCRATCH_TOTAL (OFF_FFY + SZ_TOK)

__device__ float g_scratch[SCRATCH_TOTAL];

// ---------------------------------------------------------------------------
// PTX helpers
// ---------------------------------------------------------------------------
__device__ __forceinline__ void mma_tf32(
    float& c0, float& c1, float& c2, float& c3,
    uint32_t a0, uint32_t a1, uint32_t a2, uint32_t a3,
    uint32_t b0, uint32_t b1)
{
    asm volatile(
        "mma.sync.aligned.m16n8k8.row.col.f32.tf32.tf32.f32 "
        "{%0,%1,%2,%3}, {%4,%5,%6,%7}, {%8,%9}, {%0,%1,%2,%3};"
        : "+f"(c0), "+f"(c1), "+f"(c2), "+f"(c3)
        : "r"(a0), "r"(a1), "r"(a2), "r"(a3), "r"(b0), "r"(b1));
}

__device__ __forceinline__ uint32_t smem_u32(const void* p) {
    uint32_t a;
    asm("{ .reg .u64 t; cvta.to.shared.u64 t, %1; cvt.u32.u64 %0, t; }" : "=r"(a) : "l"(p));
    return a;
}
__device__ __forceinline__ void cp16(uint32_t dst, const void* src) {
    asm volatile("cp.async.cg.shared.global [%0], [%1], 16;" :: "r"(dst), "l"(src));
}
__device__ __forceinline__ void cp_commit() {
    asm volatile("cp.async.commit_group;" ::: "memory");
}
template<int N>
__device__ __forceinline__ void cp_wait() {
    asm volatile("cp.async.wait_group %0;" :: "n"(N) : "memory");
}

// SMEM: 3 stages, each stage = A tile (128x32 fp32, 128B/row, XOR-swizzled)
// followed by B tile. Stage stride 32KB. Total 96KB.
#define STAGES 3
#define STAGE_BYTES 32768
#define BTILE_OFF 16384
#define SMEM_BYTES (STAGES * STAGE_BYTES)

// ---------------------------------------------------------------------------
// TF32 tensor-core GEMM: D(128x128 tile) = act(scale * A @ B^T + bias)
// A: (M x K) row-major fp32 (+ bz*sA). B: (N x K) row-major fp32 (+ bz*sB).
// OUTMAP: 0 plain (ldc,sC); 1 QKV head-scatter; 2 AV head-recombine; 3 V-transpose
// ---------------------------------------------------------------------------
template<int OUTMAP, bool RELU>
__global__ __launch_bounds__(256, 2) void tgemm(
    const float* __restrict__ A, int lda, long sA,
    const float* __restrict__ Bm, int ldb, long sB,
    const float* __restrict__ bias,
    float* __restrict__ Co, int ldc, long sC,
    int K, float scale)
{
    extern __shared__ float sm[];
    const uint32_t sbase = smem_u32(sm);

    const int t   = threadIdx.x;
    const int wid = t >> 5;
    const int lid = t & 31;
    const int g   = lid >> 2;       // 0..7
    const int t4  = lid & 3;        // 0..3
    const int wm  = wid & 3;        // warp row: rows wm*32..+31
    const int wn  = wid >> 2;       // warp col: cols wn*64..+63

    const int bz = blockIdx.z;
    const int m0 = blockIdx.y << 7;
    const int n0 = blockIdx.x << 7;
    A  += (long)bz * sA;
    Bm += (long)bz * sB;

    // loader geometry: idx = i*256 + t -> row = idx>>3 (0..127), c4 = idx&7 (16B unit)
    const int r_ld  = t >> 3;
    const int c4_ld = t & 7;

    auto issue_stage = [&](int c, int s) {
        const int k0 = c << 5;
        const uint32_t stage = sbase + s * STAGE_BYTES;
#pragma unroll
        for (int i = 0; i < 4; i++) {
            const int r  = r_ld + i * 32;
            const uint32_t doff = (uint32_t)(r << 7) + (uint32_t)((c4_ld ^ (r & 7)) << 4);
            cp16(stage + doff,              A  + (long)(m0 + r) * lda + k0 + (c4_ld << 2));
            cp16(stage + BTILE_OFF + doff,  Bm + (long)(n0 + r) * ldb + k0 + (c4_ld << 2));
        }
        cp_commit();
    };

    float acc[2][8][4];
#pragma unroll
    for (int mt = 0; mt < 2; mt++)
#pragma unroll
        for (int nt = 0; nt < 8; nt++)
#pragma unroll
            for (int i = 0; i < 4; i++) acc[mt][nt][i] = 0.f;

    const int nch = K >> 5;

    // prologue: fill STAGES-1 stages
#pragma unroll
    for (int c = 0; c < STAGES - 1; c++)
        if (c < nch) issue_stage(c, c);

    for (int c = 0; c < nch; c++) {
        const int s = c % STAGES;
        cp_wait<STAGES - 2>();
        __syncthreads();

        // issue next stage early (overlaps with compute below)
        if (c + STAGES - 1 < nch) issue_stage(c + STAGES - 1, (c + STAGES - 1) % STAGES);

        const float* Ab = sm + s * (STAGE_BYTES / 4);
        const float* Bb = Ab + (BTILE_OFF / 4);

#pragma unroll
        for (int kk = 0; kk < 4; kk++) {
            const int u0 = (2 * kk) ^ g;      // swizzled 16B-unit (row&7 == g for all frag rows)
            const int u1 = u0 ^ 1;
            uint32_t af[2][4];
#pragma unroll
            for (int mt = 0; mt < 2; mt++) {
                const int ra = wm * 32 + mt * 16 + g;
                af[mt][0] = __float_as_uint(Ab[(ra)     * 32 + u0 * 4 + t4]);
                af[mt][1] = __float_as_uint(Ab[(ra + 8) * 32 + u0 * 4 + t4]);
                af[mt][2] = __float_as_uint(Ab[(ra)     * 32 + u1 * 4 + t4]);
                af[mt][3] = __float_as_uint(Ab[(ra + 8) * 32 + u1 * 4 + t4]);
            }
#pragma unroll
            for (int nt = 0; nt < 8; nt++) {
                const int rb = wn * 64 + nt * 8 + g;
                uint32_t b0 = __float_as_uint(Bb[rb * 32 + u0 * 4 + t4]);
                uint32_t b1 = __float_as_uint(Bb[rb * 32 + u1 * 4 + t4]);
#pragma unroll
                for (int mt = 0; mt < 2; mt++)
                    mma_tf32(acc[mt][nt][0], acc[mt][nt][1], acc[mt][nt][2], acc[mt][nt][3],
                             af[mt][0], af[mt][1], af[mt][2], af[mt][3], b0, b1);
            }
        }
        __syncthreads();
    }

    // ---------------- epilogue ----------------
    auto outoff = [&](int m, int n) -> long {
        if constexpr (OUTMAP == 0) {
            return (long)bz * sC + (long)m * ldc + n;
        } else if constexpr (OUTMAP == 1) {
            int b = m >> 10, p = m & 1023;
            int cq = n >> 3, h = n & 7;
            return (((long)(b * HH + h) * PP + p) << 7) + cq;
        } else if constexpr (OUTMAP == 2) {
            int b = bz >> 3, h = bz & 7;
            return ((long)(b * PP + m) << 10) + (n << 3) + h;
        } else {
            int b = m >> 10, p = m & 1023;
            int cq = n >> 3, h = n & 7;
            return (((long)(b * HH + h) * CC + cq) << 10) + p;
        }
    };

#pragma unroll
    for (int mt = 0; mt < 2; mt++) {
        const int r0 = m0 + wm * 32 + mt * 16 + g;
#pragma unroll
        for (int nt = 0; nt < 8; nt++) {
            const int col = n0 + wn * 64 + nt * 8 + t4 * 2;
            float v0 = acc[mt][nt][0] * scale;
            float v1 = acc[mt][nt][1] * scale;
            float v2 = acc[mt][nt][2] * scale;
            float v3 = acc[mt][nt][3] * scale;
            if (bias) {
                float bi0 = bias[col], bi1 = bias[col + 1];
                v0 += bi0; v1 += bi1; v2 += bi0; v3 += bi1;
            }
            if (RELU) {
                v0 = fmaxf(v0, 0.f); v1 = fmaxf(v1, 0.f);
                v2 = fmaxf(v2, 0.f); v3 = fmaxf(v3, 0.f);
            }
            if constexpr (OUTMAP == 0) {
                *(float2*)(Co + outoff(r0, col))     = make_float2(v0, v1);
                *(float2*)(Co + outoff(r0 + 8, col)) = make_float2(v2, v3);
            } else {
                Co[outoff(r0, col)]         = v0;
                Co[outoff(r0, col + 1)]     = v1;
                Co[outoff(r0 + 8, col)]     = v2;
                Co[outoff(r0 + 8, col + 1)] = v3;
            }
        }
    }
}

// ---------------------------------------------------------------------------
// Double softmax over one (bh, query) row: 1024 = (m=64, g=16).
// ---------------------------------------------------------------------------
__global__ __launch_bounds__(128) void softmax2_kernel(float* __restrict__ S)
{
    float* row = S + ((long)blockIdx.y * PP + blockIdx.x) * PP;
    __shared__ float sp[64 * 17];
    const int t = threadIdx.x;

    float4 v0 = *(const float4*)(row + t * 8);
    float4 v1 = *(const float4*)(row + t * 8 + 4);
    float* dst = sp + (t >> 1) * 17 + ((t & 1) << 3);
    dst[0] = v0.x; dst[1] = v0.y; dst[2] = v0.z; dst[3] = v0.w;
    dst[4] = v1.x; dst[5] = v1.y; dst[6] = v1.z; dst[7] = v1.w;
    __syncthreads();

    {
        const int g = t >> 3, ii = t & 7;
        float mx = -1e30f;
#pragma unroll
        for (int jm = ii; jm < 64; jm += 8) mx = fmaxf(mx, sp[jm * 17 + g]);
#pragma unroll
        for (int o = 4; o; o >>= 1) mx = fmaxf(mx, __shfl_xor_sync(0xffffffffu, mx, o));
        float sum = 0.f;
#pragma unroll
        for (int jm = ii; jm < 64; jm += 8) {
            float e = __expf(sp[jm * 17 + g] - mx);
            sp[jm * 17 + g] = e;
            sum += e;
        }
#pragma unroll
        for (int o = 4; o; o >>= 1) sum += __shfl_xor_sync(0xffffffffu, sum, o);
        float inv = 1.f / sum;
#pragma unroll
        for (int jm = ii; jm < 64; jm += 8) sp[jm * 17 + g] *= inv;
    }
    __syncthreads();

    if (t < 64) {
        float* r = sp + t * 17;
        float mx2 = -1e30f;
#pragma unroll
        for (int g2 = 0; g2 < 16; g2++) mx2 = fmaxf(mx2, r[g2]);
        float s2 = 0.f;
#pragma unroll
        for (int g2 = 0; g2 < 16; g2++) {
            float e = __expf(r[g2] - mx2);
            r[g2] = e;
            s2 += e;
        }
        float i2 = 1.f / s2;
#pragma unroll
        for (int g2 = 0; g2 < 16; g2++) r[g2] *= i2;
    }
    __syncthreads();

    const float* src = sp + (t >> 1) * 17 + ((t & 1) << 3);
    *(float4*)(row + t * 8)     = make_float4(src[0], src[1], src[2], src[3]);
    *(float4*)(row + t * 8 + 4) = make_float4(src[4], src[5], src[6], src[7]);
}

// ---------------------------------------------------------------------------
// out = LayerNorm(A + R) * gamma + beta
// ---------------------------------------------------------------------------
__global__ __launch_bounds__(128) void add_ln_kernel(
    const float* __restrict__ A, const float* __restrict__ R,
    const float* __restrict__ gam, const float* __restrict__ bet,
    float* __restrict__ out)
{
    const long base = (long)blockIdx.x * CC;
    const int t = threadIdx.x;
    __shared__ float red[8];

    float v = A[base + t] + R[base + t];

    float s = v;
#pragma unroll
    for (int o = 16; o; o >>= 1) s += __shfl_xor_sync(0xffffffffu, s, o);
    if ((t & 31) == 0) red[t >> 5] = s;
    __syncthreads();
    const float mean = (red[0] + red[1] + red[2] + red[3]) * (1.f / CC);

    const float d = v - mean;
    float s2 = d * d;
#pragma unroll
    for (int o = 16; o; o >>= 1) s2 += __shfl_xor_sync(0xffffffffu, s2, o);
    if ((t & 31) == 0) red[4 + (t >> 5)] = s2;
    __syncthreads();
    const float var = (red[4] + red[5] + red[6] + red[7]) * (1.f / CC);

    out[base + t] = d * rsqrtf(var + 1e-5f) * gam[t] + bet[t];
}

// ---------------------------------------------------------------------------
extern "C" void kernel_launch(void* const* d_in, const int* in_sizes, int n_in,
                              void* d_out, int out_size)
{
    const float* x     = (const float*)d_in[0];
    const float* wq    = (const float*)d_in[1];
    const float* bq    = (const float*)d_in[2];
    const float* wk    = (const float*)d_in[3];
    const float* bk    = (const float*)d_in[4];
    const float* wv    = (const float*)d_in[5];
    const float* bv    = (const float*)d_in[6];
    const float* wo    = (const float*)d_in[7];
    const float* bo    = (const float*)d_in[8];
    const float* ln1_g = (const float*)d_in[9];
    const float* ln1_b = (const float*)d_in[10];
    const float* w1    = (const float*)d_in[11];
    const float* b1    = (const float*)d_in[12];
    const float* w2    = (const float*)d_in[13];
    const float* b2    = (const float*)d_in[14];
    const float* ln2_g = (const float*)d_in[15];
    const float* ln2_b = (const float*)d_in[16];
    float* out = (float*)d_out;

    float* scr = nullptr;
    cudaGetSymbolAddress((void**)&scr, g_scratch);
    float* q   = scr + OFF_Q;
    float* k   = scr + OFF_K;
    float* vt  = scr + OFF_V;
    float* sS  = scr + OFF_S;
    float* zc  = scr + OFF_ZC;
    float* ao  = scr + OFF_AO;
    float* z1  = scr + OFF_Z1;
    float* h1  = scr + OFF_H1;
    float* ffy = scr + OFF_FFY;

    cudaFuncSetAttribute(tgemm<0, false>, cudaFuncAttributeMaxDynamicSharedMemorySize, SMEM_BYTES);
    cudaFuncSetAttribute(tgemm<0, true>,  cudaFuncAttributeMaxDynamicSharedMemorySize, SMEM_BYTES);
    cudaFuncSetAttribute(tgemm<1, false>, cudaFuncAttributeMaxDynamicSharedMemorySize, SMEM_BYTES);
    cudaFuncSetAttribute(tgemm<2, false>, cudaFuncAttributeMaxDynamicSharedMemorySize, SMEM_BYTES);
    cudaFuncSetAttribute(tgemm<3, false>, cudaFuncAttributeMaxDynamicSharedMemorySize, SMEM_BYTES);

    const float inv_sqrt_c = 0.08838834764831845f;

    // 1-3: QKV projections (8192 x 1024 x 128)
    tgemm<1, false><<<dim3(8, 64, 1), 256, SMEM_BYTES>>>(
        x, CC, 0, wq, CC, 0, bq, q, 0, 0, CC, 1.f);
    tgemm<1, false><<<dim3(8, 64, 1), 256, SMEM_BYTES>>>(
        x, CC, 0, wk, CC, 0, bk, k, 0, 0, CC, 1.f);
    tgemm<3, false><<<dim3(8, 64, 1), 256, SMEM_BYTES>>>(
        x, CC, 0, wv, CC, 0, bv, vt, 0, 0, CC, 1.f);

    // 4: scores = Q @ K^T / sqrt(C)  (64 batches of 1024x1024x128)
    tgemm<0, false><<<dim3(8, 8, 64), 256, SMEM_BYTES>>>(
        q, CC, (long)PP * CC, k, CC, (long)PP * CC, nullptr,
        sS, PP, (long)PP * PP, CC, inv_sqrt_c);

    // 5: double softmax
    softmax2_kernel<<<dim3(PP, 64), 128>>>(sS);

    // 6: Z = A @ Vt^T  (64 batches of 1024x128x1024), head-recombine -> zc
    tgemm<2, false><<<dim3(1, 8, 64), 256, SMEM_BYTES>>>(
        sS, PP, (long)PP * PP, vt, PP, (long)CC * PP, nullptr,
        zc, 0, 0, PP, 1.f);

    // 7: attn_out = zc @ wo^T + bo  (8192x128x1024)
    tgemm<0, false><<<dim3(1, 64, 1), 256, SMEM_BYTES>>>(
        zc, CH, 0, wo, CH, 0, bo, ao, CC, 0, CH, 1.f);

    // 8: z1 = LN1(attn_out + x)
    add_ln_kernel<<<NTOK, 128>>>(ao, x, ln1_g, ln1_b, z1);

    // 9: h1 = relu(z1 @ w1^T + b1)  (8192x512x128)
    tgemm<0, true><<<dim3(4, 64, 1), 256, SMEM_BYTES>>>(
        z1, CC, 0, w1, CC, 0, b1, h1, FFN, 0, CC, 1.f);

    // 10: ffy = h1 @ w2^T + b2  (8192x128x512)
    tgemm<0, false><<<dim3(1, 64, 1), 256, SMEM_BYTES>>>(
        h1, FFN, 0, w2, FFN, 0, b2, ffy, CC, 0, FFN, 1.f);

    // 11: out = LN2(ffy + z1)
    add_ln_kernel<<<NTOK, 128>>>(ffy, z1, ln2_g, ln2_b, out);
}